// round 16
// baseline (speedup 1.0000x reference)
#include <cuda_runtime.h>
#include <cuda_fp16.h>
#include <cstdint>

#define B_  4
#define S_  2048
#define D_  1024
#define H_  16
#define DH  64

// Scratch (device globals -- no allocations allowed).
// k-dims stored with perm16: within each 16-block, memory position
// 4t+r (t=0..3, r=0..3) holds dim 2t + r + (r>=2 ? 6 : 0).
__device__ __half g_qh[(size_t)B_*H_*S_*DH];     // perm16 q
__device__ __half g_kh[(size_t)B_*H_*S_*DH];     // perm16 k (then folded k')
__device__ __half g_vh[(size_t)B_*H_*DH*S_];     // V^T: [bh][d][j perm16]
__device__ __half g_xh[(size_t)B_*S_*D_];        // perm16 x
__device__ __half g_wh[(size_t)2*D_*D_];         // perm16 W
__device__ float  g_kpart[256*64];               // ksum partials

// ---------------------------------------------------------------------------
// helpers
// ---------------------------------------------------------------------------
__device__ __forceinline__ uint32_t smem_u32(const void* p) {
    uint32_t a;
    asm("{ .reg .u64 t; cvta.to.shared.u64 t, %1; cvt.u32.u64 %0, t; }"
        : "=r"(a) : "l"(p));
    return a;
}
#define CP_ASYNC16(dst, src) \
    asm volatile("cp.async.cg.shared.global [%0], [%1], 16;" :: "r"(dst), "l"(src) : "memory")
#define CP_COMMIT() asm volatile("cp.async.commit_group;" ::: "memory")
#define CP_WAIT(N)  asm volatile("cp.async.wait_group %0;" :: "n"(N) : "memory")

// fp16 mma m16n8k16 (row.col), fp32 accum, D += A*B
__device__ __forceinline__ void mma_f16(float* d, const uint32_t* a, const uint32_t* b)
{
    asm volatile(
        "mma.sync.aligned.m16n8k16.row.col.f32.f16.f16.f32 "
        "{%0,%1,%2,%3}, {%4,%5,%6,%7}, {%8,%9}, {%0,%1,%2,%3};"
        : "+f"(d[0]), "+f"(d[1]), "+f"(d[2]), "+f"(d[3])
        : "r"(a[0]), "r"(a[1]), "r"(a[2]), "r"(a[3]), "r"(b[0]), "r"(b[1]));
}

// selu on a pair of QK' accumulators (d = log2e * s)
__device__ __forceinline__ uint32_t seluh2(float d0, float d1)
{
    const __half2 z   = __float2half2_rn(0.f);
    const __half2 la  = __float2half2_rn(1.7580993408473766f);    // lam*alpha
    const __half2 nla = __float2half2_rn(-1.7580993408473766f);
    const __half2 cp  = __float2half2_rn(0.72829048f);            // lam*ln2
    __half2 hd = __floats2half2_rn(d0, d1);
    __half2 dmin = __hmin2(hd, z);
    __half2 dmax = __hmax2(hd, z);
    __half2 e = h2exp2(dmin);
    __half2 r = __hfma2(la, e, nla);
    r = __hfma2(cp, dmax, r);
    return *reinterpret_cast<uint32_t*>(&r);
}

__device__ __forceinline__ int orig16(int r)    // perm16 inverse map
{
    const int t = r >> 2, m = r & 3;
    return 2 * t + m + ((m >= 2) ? 6 : 0);
}

// ---------------------------------------------------------------------------
// Kernel 0: fp16 + perm16 convert W only (x handled by vtr_kernel)
// ---------------------------------------------------------------------------
#define WB16 ((size_t)2*D_*D_/16)        // 131072

__global__ __launch_bounds__(256) void cvt_kernel(const float* __restrict__ W)
{
    const size_t i = (size_t)blockIdx.x * 256 + threadIdx.x;
    if (i >= WB16) return;
    const float* src = W + i * 16;
    __half* dst = g_wh + i * 16;
    float v[16];
#pragma unroll
    for (int q = 0; q < 4; q++) *(float4*)&v[q*4] = *(const float4*)(src + q*4);
    __half h[16];
#pragma unroll
    for (int q = 0; q < 16; q++) h[q] = __float2half(v[orig16(q)]);
    *(uint4*)dst       = *(uint4*)&h[0];
    *(uint4*)(dst + 8) = *(uint4*)&h[8];
}

// ---------------------------------------------------------------------------
// Kernel 0b: from each x tile, emit BOTH g_vh (V^T j-perm16) and g_xh
// (perm16 rows).  x read exactly once.
// ---------------------------------------------------------------------------
__global__ __launch_bounds__(256) void vtr_kernel(const float* __restrict__ x)
{
    __shared__ float t[128][65];
    const int b = blockIdx.z, h = blockIdx.y, j0 = blockIdx.x * 128;
    const int tid = threadIdx.x;
#pragma unroll
    for (int i = 0; i < 8; i++) {
        const int idx = tid + i * 256;
        const int row = idx >> 4, c4 = (idx & 15) * 4;
        float4 v = *(const float4*)(x + ((size_t)b * S_ + j0 + row) * D_ + h * 64 + c4);
        t[row][c4 + 0] = v.x; t[row][c4 + 1] = v.y;
        t[row][c4 + 2] = v.z; t[row][c4 + 3] = v.w;
    }
    __syncthreads();

    {
        const int d = tid >> 2;
        const int pg = (tid & 3) * 32;
        __half* dst = g_vh + ((size_t)(b * H_ + h) * DH + d) * S_ + j0 + pg;
#pragma unroll
        for (int u = 0; u < 4; u++) {
            __half h8[8];
#pragma unroll
            for (int q = 0; q < 8; q++) {
                const int p = pg + u * 8 + q;
                const int j = (p & ~15) + orig16(p & 15);
                h8[q] = __float2half(t[j][d]);
            }
            *(uint4*)(dst + u * 8) = *(uint4*)h8;
        }
    }

#pragma unroll
    for (int cci = 0; cci < 2; cci++) {
        const int cc = tid * 2 + cci;
        const int row = cc >> 2;
        const int blk = cc & 3;
        __half h16[16];
#pragma unroll
        for (int q = 0; q < 16; q++)
            h16[q] = __float2half(t[row][blk * 16 + orig16(q)]);
        __half* dst = g_xh + ((size_t)b * S_ + j0 + row) * D_ + h * 64 + blk * 16;
        *(uint4*)dst       = *(uint4*)&h16[0];
        *(uint4*)(dst + 8) = *(uint4*)&h16[8];
    }
}

// ---------------------------------------------------------------------------
// Kernel 1: fused q/k projection, fp16 m16n8k16, 3-stage single-sync.
// ---------------------------------------------------------------------------
#define PJ_LDH   48
#define PJ_MAT_B (128 * 96)
#define PJ_STG_B (2 * PJ_MAT_B)              // 24576 B per stage
#define PJ_SMEM  73728                       // 3 stages (>= Cs 67584)
#define PJ_LDC   132

__global__ __launch_bounds__(256, 2) void proj_kernel(const float* __restrict__ bias)
{
    extern __shared__ char smc[];
    float* Cs = (float*)smc;
    __shared__ float sBias[128];

    const int tid = threadIdx.x;
    const int m0 = blockIdx.y * 128;
    const int n0 = blockIdx.x * 128;
    const int wid = tid >> 5;
    const int lane = tid & 31;
    const int gid = lane >> 2;
    const int tig = lane & 3;
    const int wm = wid & 1;
    const int wn = wid >> 1;

    if (tid < 128) sBias[tid] = bias[n0 + tid];

    float acc[4][4][4];
#pragma unroll
    for (int mi = 0; mi < 4; mi++)
#pragma unroll
        for (int ni = 0; ni < 4; ni++)
#pragma unroll
            for (int r = 0; r < 4; r++) acc[mi][ni][r] = 0.f;

    const uint32_t sbase = smem_u32(smc);

    auto load_stage = [&](int s, int k0) {
        const uint32_t aB = sbase + s * PJ_STG_B;
        const uint32_t bB = aB + PJ_MAT_B;
#pragma unroll
        for (int i = 0; i < 2; i++) {
            const int idx = tid + i * 256;
            const int row = idx >> 2, c = idx & 3;
            CP_ASYNC16(aB + row * 96 + c * 16,
                       g_xh + (size_t)(m0 + row) * D_ + k0 + c * 8);
        }
#pragma unroll
        for (int i = 0; i < 2; i++) {
            const int idx = tid + i * 256;
            const int row = idx >> 2, c = idx & 3;
            CP_ASYNC16(bB + row * 96 + c * 16,
                       g_wh + (size_t)(n0 + row) * D_ + k0 + c * 8);
        }
        CP_COMMIT();
    };

    load_stage(0, 0);
    load_stage(1, 32);

    const int NKC = D_ / 32;
    for (int kc = 0; kc < NKC; kc++) {
        if (kc < NKC - 1) CP_WAIT(1); else CP_WAIT(0);
        __syncthreads();
        if (kc + 2 < NKC) load_stage((kc + 2) % 3, (kc + 2) * 32);

        const __half* A  = (const __half*)(smc + (kc % 3) * PJ_STG_B);
        const __half* Bp = A + 128 * PJ_LDH;
#pragma unroll
        for (int kg = 0; kg < 2; kg++) {
            uint32_t a[4][4];
#pragma unroll
            for (int mi = 0; mi < 4; mi++) {
                const __half* ra = A + (wm * 64 + mi * 16 + gid) * PJ_LDH + kg * 16 + tig * 4;
                uint2 lo = *(const uint2*)ra;
                uint2 hi = *(const uint2*)(ra + 8 * PJ_LDH);
                a[mi][0] = lo.x; a[mi][1] = hi.x; a[mi][2] = lo.y; a[mi][3] = hi.y;
            }
            uint32_t bf[4][2];
#pragma unroll
            for (int ni = 0; ni < 4; ni++) {
                const __half* rb = Bp + (wn * 32 + ni * 8 + gid) * PJ_LDH + kg * 16 + tig * 4;
                uint2 f = *(const uint2*)rb;
                bf[ni][0] = f.x; bf[ni][1] = f.y;
            }
#pragma unroll
            for (int mi = 0; mi < 4; mi++)
#pragma unroll
                for (int ni = 0; ni < 4; ni++)
                    mma_f16(acc[mi][ni], a[mi], bf[ni]);
        }
    }
    __syncthreads();

    // ---- epilogue: acc -> Cs -> perm16 fp16 scatter to g_qh / g_kh ----
#pragma unroll
    for (int mi = 0; mi < 4; mi++)
#pragma unroll
        for (int ni = 0; ni < 4; ni++) {
            const int r = wm * 64 + mi * 16 + gid;
            const int c = wn * 32 + ni * 8 + 2 * tig;
            *(float2*)&Cs[r * PJ_LDC + c]       = make_float2(acc[mi][ni][0], acc[mi][ni][1]);
            *(float2*)&Cs[(r + 8) * PJ_LDC + c] = make_float2(acc[mi][ni][2], acc[mi][ni][3]);
        }
    __syncthreads();

    {
        const int r    = tid >> 1;
        const int hsel = tid & 1;
        const int m = m0 + r;
        const int bb = m >> 11;
        const int s_idx = m & 2047;
        const int hh = n0 >> 7;
        const size_t base = (((size_t)bb * H_ + hh) * S_ + s_idx) * DH;
        const float* cr = Cs + r * PJ_LDC;
#pragma unroll
        for (int bi = 0; bi < 2; bi++) {
            const int bk = hsel * 2 + bi;
            __half qh[16], kh[16];
#pragma unroll
            for (int q = 0; q < 16; q++) {
                const int dorig = bk * 16 + orig16(q);
                qh[q] = __float2half(cr[2 * dorig]     + sBias[2 * dorig]);
                kh[q] = __float2half(cr[2 * dorig + 1] + sBias[2 * dorig + 1]);
            }
            *(uint4*)(g_qh + base + bk * 16)     = *(uint4*)&qh[0];
            *(uint4*)(g_qh + base + bk * 16 + 8) = *(uint4*)&qh[8];
            *(uint4*)(g_kh + base + bk * 16)     = *(uint4*)&kh[0];
            *(uint4*)(g_kh + base + bk * 16 + 8) = *(uint4*)&kh[8];
        }
    }
}

// ---------------------------------------------------------------------------
// Kernel 2a: per-chunk ksum partials; 2b: kadj folds mean+scale*log2e into K
// (reads g_kpart directly -- ksum2/g_ksum eliminated)
// ---------------------------------------------------------------------------
__global__ __launch_bounds__(256) void ksum1_kernel()
{
    __shared__ float red[256];
    const int blk = blockIdx.x;
    const int bh = blk >> 2, c = blk & 3;
    const int t = threadIdx.x;
    const int d = t & 63;
    const int sub = t >> 6;
    const __half* base = g_kh + (size_t)bh * S_ * DH;
    const int j0 = c * 512 + sub * 128, j1 = j0 + 128;
    float s = 0.f;
    for (int j = j0; j < j1; j++) s += __half2float(base[(size_t)j * DH + d]);
    red[t] = s;
    __syncthreads();
    if (t < 64)
        g_kpart[blk * 64 + t] = red[t] + red[64 + t] + red[128 + t] + red[192 + t];
}

__global__ __launch_bounds__(256) void kadj_kernel()
{
    __shared__ float sk[64];
    const int bh  = blockIdx.y;
    const int seg = blockIdx.x;
    const int tid = threadIdx.x;
    if (tid < 64) {
        const float s = g_kpart[(bh * 4 + 0) * 64 + tid] + g_kpart[(bh * 4 + 1) * 64 + tid]
                      + g_kpart[(bh * 4 + 2) * 64 + tid] + g_kpart[(bh * 4 + 3) * 64 + tid];
        sk[tid] = s * (1.f / (float)S_);
    }
    __syncthreads();
    const float KF = 0.125f * 1.4426950408889634f;   // SCALE * log2(e)
    __half* base = g_kh + (size_t)bh * S_ * DH + (size_t)seg * 256 * DH;
    for (int i = tid; i < 2048; i += 256) {
        __half h[8];
        *(uint4*)h = *(const uint4*)(base + i * 8);
        const int p0 = (i * 8) & 63;
#pragma unroll
        for (int q = 0; q < 8; q++)
            h[q] = __float2half((__half2float(h[q]) - sk[p0 + q]) * KF);
        *(uint4*)(base + i * 8) = *(uint4*)h;
    }
}

// ---------------------------------------------------------------------------
// Kernel 3: fused attention, fp16 m16n8k16, mean pre-folded into K.
// 256-row CTA, 8 warps x 32 rows (full j=64 per iter), 1 CTA/SM, 256 threads.
// Q fragments hoisted to registers (reg budget 255 at occupancy 1).
// K/V fragments serve BOTH 16-row halves -> smem traffic per output halved.
// smem: qs 256x80h (40960), ks 2x64x80h (20480), vs 2x64x80h (20480) = 81920
// ps (256x68 f32 = 69632) overlays the base post-loop.
// ---------------------------------------------------------------------------
#define AT_LDH  80
#define AT_QS_B (256 * AT_LDH * 2)           // 40960
#define AT_KS_B (64 * AT_LDH * 2)            // 10240
#define AT_KS_OFF AT_QS_B                    // 40960
#define AT_VS_OFF (AT_QS_B + 2 * AT_KS_B)    // 61440
#define AT_SMEM (AT_VS_OFF + 2 * AT_KS_B)    // 81920

__global__ __launch_bounds__(256, 1) void attn_kernel(float* __restrict__ out)
{
    extern __shared__ char smc[];
    __half* qs = (__half*)smc;
    float*  ps = (float*)smc;                // overlay, post-loop only

    const int b  = blockIdx.z;
    const int h  = blockIdx.y;
    const int s0 = blockIdx.x * 256;
    const int tid = threadIdx.x;
    const int wid = tid >> 5;
    const int lane = tid & 31;
    const int gid = lane >> 2;
    const int tig = lane & 3;
    const int wm = wid;                      // 0..7, rows wm*32 .. wm*32+31

    const size_t bh = (size_t)b * H_ + h;
    const __half* qg = g_qh + bh * S_ * DH;
    const __half* kg = g_kh + bh * S_ * DH;
    const __half* vg = g_vh + bh * DH * S_;

    const uint32_t qsB = smem_u32(smc);
    const uint32_t ksB = qsB + AT_KS_OFF;
    const uint32_t vsB = qsB + AT_VS_OFF;

    auto load_kv = [&](int buf, int j0) {
        const uint32_t kB = ksB + buf * AT_KS_B;
        const uint32_t vB = vsB + buf * AT_KS_B;
#pragma unroll
        for (int i = 0; i < 2; i++) {
            const int idx = tid + i * 256;
            const int row = idx >> 3, c = idx & 7;
            CP_ASYNC16(kB + row * 160 + c * 16,
                       kg + (size_t)(j0 + row) * DH + c * 8);
        }
#pragma unroll
        for (int i = 0; i < 2; i++) {
            const int idx = tid + i * 256;
            const int row = idx >> 3, c = idx & 7;   // row = d
            CP_ASYNC16(vB + row * 160 + c * 16,
                       vg + (size_t)row * S_ + j0 + c * 8);
        }
    };

    // ---- prologue: Q (256 rows) + K/V tile 0 ----
#pragma unroll
    for (int i = 0; i < 8; i++) {
        const int idx = tid + i * 256;               // 0..2047
        const int row = idx >> 3, c = idx & 7;
        CP_ASYNC16(qsB + row * 160 + c * 16,
                   qg + (size_t)(s0 + row) * DH + c * 8);
    }
    load_kv(0, 0);
    CP_COMMIT();
    CP_WAIT(0);
    __syncthreads();

    // ---- hoist Q fragments into registers (constant over j-loop) ----
    uint32_t aq[2][4][4];
#pragma unroll
    for (int mi = 0; mi < 2; mi++)
#pragma unroll
        for (int g = 0; g < 4; g++) {
            const __half* ra = qs + (wm * 32 + mi * 16 + gid) * AT_LDH + g * 16 + tig * 4;
            uint2 lo = *(const uint2*)ra;
            uint2 hi = *(const uint2*)(ra + 8 * AT_LDH);
            aq[mi][g][0] = lo.x; aq[mi][g][1] = hi.x;
            aq[mi][g][2] = lo.y; aq[mi][g][3] = hi.y;
        }

    float oacc[2][8][4];
#pragma unroll
    for (int mi = 0; mi < 2; mi++)
#pragma unroll
        for (int nt = 0; nt < 8; nt++)
#pragma unroll
            for (int r = 0; r < 4; r++) oacc[mi][nt][r] = 0.f;

    const int NJT = S_ / 64;                 // 32
    for (int jt = 0; jt < NJT; jt++) {
        const int buf = jt & 1;
        if (jt > 0) {
            CP_WAIT(0);
            __syncthreads();                 // K/V[buf] ready; reads of buf^1 done
        }
        if (jt + 1 < NJT) {
            load_kv(buf ^ 1, (jt + 1) * 64);
            CP_COMMIT();
        }

        const __half* kss = (const __half*)(smc + AT_KS_OFF + buf * AT_KS_B);
        const __half* vss = (const __half*)(smc + AT_VS_OFF + buf * AT_KS_B);

        // ---- d = Q K'^T : 32m x 64j ----
        float d[2][8][4];
#pragma unroll
        for (int mi = 0; mi < 2; mi++)
#pragma unroll
            for (int tn = 0; tn < 8; tn++)
#pragma unroll
                for (int r = 0; r < 4; r++) d[mi][tn][r] = 0.f;

#pragma unroll
        for (int g = 0; g < 4; g++) {
#pragma unroll
            for (int tn = 0; tn < 8; tn++) {
                const __half* rb = kss + (tn * 8 + gid) * AT_LDH + g * 16 + tig * 4;
                uint2 f = *(const uint2*)rb;
                uint32_t bb2[2] = { f.x, f.y };
                mma_f16(d[0][tn], aq[0][g], bb2);
                mma_f16(d[1][tn], aq[1][g], bb2);
            }
        }

        // ---- half2 selu; packs feed AV A-fragments directly ----
        uint32_t av[2][4][4];
#pragma unroll
        for (int mi = 0; mi < 2; mi++)
#pragma unroll
            for (int u = 0; u < 4; u++) {
                av[mi][u][0] = seluh2(d[mi][2*u][0],   d[mi][2*u][1]);
                av[mi][u][1] = seluh2(d[mi][2*u][2],   d[mi][2*u][3]);
                av[mi][u][2] = seluh2(d[mi][2*u+1][0], d[mi][2*u+1][1]);
                av[mi][u][3] = seluh2(d[mi][2*u+1][2], d[mi][2*u+1][3]);
            }

        // ---- oacc += A @ V ; each V fragment serves both row-halves ----
#pragma unroll
        for (int nt = 0; nt < 8; nt++) {
#pragma unroll
            for (int u = 0; u < 4; u++) {
                const __half* rv = vss + (nt * 8 + gid) * AT_LDH + u * 16 + tig * 4;
                uint2 f = *(const uint2*)rv;
                uint32_t bb2[2] = { f.x, f.y };
                mma_f16(oacc[0][nt], av[0][u], bb2);
                mma_f16(oacc[1][nt], av[1][u], bb2);
            }
        }
    }

    // ---- epilogue: oacc -> ps overlay -> coalesced gmem ----
    __syncthreads();
#pragma unroll
    for (int mi = 0; mi < 2; mi++)
#pragma unroll
        for (int nt = 0; nt < 8; nt++) {
            const int r = wm * 32 + mi * 16 + gid;
            *(float2*)(ps + r * 68 + nt * 8 + 2 * tig) =
                make_float2(oacc[mi][nt][0], oacc[mi][nt][1]);
            *(float2*)(ps + (r + 8) * 68 + nt * 8 + 2 * tig) =
                make_float2(oacc[mi][nt][2], oacc[mi][nt][3]);
        }
    __syncthreads();
    {
        const float OS = 0.022097086912079608f;   // 2048^-0.5
#pragma unroll
        for (int half = 0; half < 2; half++) {
            const int r = (tid >> 1) + half * 128;
            const int seg = (tid & 1) * 32;
            const float* pr = ps + r * 68 + seg;
            float* dst = out + ((size_t)b * S_ + s0 + r) * D_ + h * DH + seg;
#pragma unroll
            for (int v = 0; v < 8; v++) {
                float4 o4 = make_float4(pr[v*4+0] * OS, pr[v*4+1] * OS,
                                        pr[v*4+2] * OS, pr[v*4+3] * OS);
                *(float4*)(dst + v * 4) = o4;
            }
        }
    }
}

// ---------------------------------------------------------------------------
extern "C" void kernel_launch(void* const* d_in, const int* in_sizes, int n_in,
                              void* d_out, int out_size)
{
    const float* x    = (const float*)d_in[0];
    const float* W    = (const float*)d_in[1];
    const float* bias = (const float*)d_in[2];
    float* out = (float*)d_out;

    cudaFuncSetAttribute(proj_kernel,
                         cudaFuncAttributeMaxDynamicSharedMemorySize, PJ_SMEM);
    cudaFuncSetAttribute(attn_kernel,
                         cudaFuncAttributeMaxDynamicSharedMemorySize, AT_SMEM);

    const int cvt_blocks = (int)((WB16 + 255) / 256);
    cvt_kernel<<<cvt_blocks, 256>>>(W);

    dim3 vg(S_ / 128, H_, B_);                       // (16, 16, 4)
    vtr_kernel<<<vg, 256>>>(x);

    dim3 pg(D_ * 2 / 128, (B_ * S_) / 128);          // (16, 64)
    proj_kernel<<<pg, 256, PJ_SMEM>>>(bias);

    ksum1_kernel<<<256, 256>>>();

    dim3 kg(8, B_ * H_);                             // (8, 64)
    kadj_kernel<<<kg, 256>>>();

    dim3 ag(S_ / 256, H_, B_);                       // (8, 16, 4)
    attn_kernel<<<ag, 256, AT_SMEM>>>(out);
}

// round 17
// speedup vs baseline: 1.0674x; 1.0674x over previous
#include <cuda_runtime.h>
#include <cuda_fp16.h>
#include <cstdint>

#define B_  4
#define S_  2048
#define D_  1024
#define H_  16
#define DH  64

// Scratch (device globals -- no allocations allowed).
// k-dims stored with perm16: within each 16-block, memory position
// 4t+r (t=0..3, r=0..3) holds dim 2t + r + (r>=2 ? 6 : 0).
__device__ __half g_qh[(size_t)B_*H_*S_*DH];     // perm16 q
__device__ __half g_kh[(size_t)B_*H_*S_*DH];     // perm16 k (then folded k')
__device__ __half g_vh[(size_t)B_*H_*DH*S_];     // V^T: [bh][d][j perm16]
__device__ __half g_xh[(size_t)B_*S_*D_];        // perm16 x
__device__ __half g_wh[(size_t)2*D_*D_];         // perm16 W
__device__ float  g_kpart[512*64];               // ksum partials

// ---------------------------------------------------------------------------
// helpers
// ---------------------------------------------------------------------------
__device__ __forceinline__ uint32_t smem_u32(const void* p) {
    uint32_t a;
    asm("{ .reg .u64 t; cvta.to.shared.u64 t, %1; cvt.u32.u64 %0, t; }"
        : "=r"(a) : "l"(p));
    return a;
}
#define CP_ASYNC16(dst, src) \
    asm volatile("cp.async.cg.shared.global [%0], [%1], 16;" :: "r"(dst), "l"(src) : "memory")
#define CP_COMMIT() asm volatile("cp.async.commit_group;" ::: "memory")
#define CP_WAIT(N)  asm volatile("cp.async.wait_group %0;" :: "n"(N) : "memory")

// fp16 mma m16n8k16 (row.col), fp32 accum, D += A*B
__device__ __forceinline__ void mma_f16(float* d, const uint32_t* a, const uint32_t* b)
{
    asm volatile(
        "mma.sync.aligned.m16n8k16.row.col.f32.f16.f16.f32 "
        "{%0,%1,%2,%3}, {%4,%5,%6,%7}, {%8,%9}, {%0,%1,%2,%3};"
        : "+f"(d[0]), "+f"(d[1]), "+f"(d[2]), "+f"(d[3])
        : "r"(a[0]), "r"(a[1]), "r"(a[2]), "r"(a[3]), "r"(b[0]), "r"(b[1]));
}

// selu on a pair of QK' accumulators (d = log2e * s)
__device__ __forceinline__ uint32_t seluh2(float d0, float d1)
{
    const __half2 z   = __float2half2_rn(0.f);
    const __half2 la  = __float2half2_rn(1.7580993408473766f);    // lam*alpha
    const __half2 nla = __float2half2_rn(-1.7580993408473766f);
    const __half2 cp  = __float2half2_rn(0.72829048f);            // lam*ln2
    __half2 hd = __floats2half2_rn(d0, d1);
    __half2 dmin = __hmin2(hd, z);
    __half2 dmax = __hmax2(hd, z);
    __half2 e = h2exp2(dmin);
    __half2 r = __hfma2(la, e, nla);
    r = __hfma2(cp, dmax, r);
    return *reinterpret_cast<uint32_t*>(&r);
}

__device__ __forceinline__ int orig16(int r)    // perm16 inverse map
{
    const int t = r >> 2, m = r & 3;
    return 2 * t + m + ((m >= 2) ? 6 : 0);
}

// ---------------------------------------------------------------------------
// Kernel 0: fp16 + perm16 convert W only (x handled by vtr_kernel)
// ---------------------------------------------------------------------------
#define WB16 ((size_t)2*D_*D_/16)        // 131072

__global__ __launch_bounds__(256) void cvt_kernel(const float* __restrict__ W)
{
    const size_t i = (size_t)blockIdx.x * 256 + threadIdx.x;
    if (i >= WB16) return;
    const float* src = W + i * 16;
    __half* dst = g_wh + i * 16;
    float v[16];
#pragma unroll
    for (int q = 0; q < 4; q++) *(float4*)&v[q*4] = *(const float4*)(src + q*4);
    __half h[16];
#pragma unroll
    for (int q = 0; q < 16; q++) h[q] = __float2half(v[orig16(q)]);
    *(uint4*)dst       = *(uint4*)&h[0];
    *(uint4*)(dst + 8) = *(uint4*)&h[8];
}

// ---------------------------------------------------------------------------
// Kernel 0b: from each x tile, emit BOTH g_vh (V^T j-perm16) and g_xh
// (perm16 rows).  x read exactly once.
// ---------------------------------------------------------------------------
__global__ __launch_bounds__(256) void vtr_kernel(const float* __restrict__ x)
{
    __shared__ float t[128][65];
    const int b = blockIdx.z, h = blockIdx.y, j0 = blockIdx.x * 128;
    const int tid = threadIdx.x;
#pragma unroll
    for (int i = 0; i < 8; i++) {
        const int idx = tid + i * 256;
        const int row = idx >> 4, c4 = (idx & 15) * 4;
        float4 v = *(const float4*)(x + ((size_t)b * S_ + j0 + row) * D_ + h * 64 + c4);
        t[row][c4 + 0] = v.x; t[row][c4 + 1] = v.y;
        t[row][c4 + 2] = v.z; t[row][c4 + 3] = v.w;
    }
    __syncthreads();

    {
        const int d = tid >> 2;
        const int pg = (tid & 3) * 32;
        __half* dst = g_vh + ((size_t)(b * H_ + h) * DH + d) * S_ + j0 + pg;
#pragma unroll
        for (int u = 0; u < 4; u++) {
            __half h8[8];
#pragma unroll
            for (int q = 0; q < 8; q++) {
                const int p = pg + u * 8 + q;
                const int j = (p & ~15) + orig16(p & 15);
                h8[q] = __float2half(t[j][d]);
            }
            *(uint4*)(dst + u * 8) = *(uint4*)h8;
        }
    }

#pragma unroll
    for (int cci = 0; cci < 2; cci++) {
        const int cc = tid * 2 + cci;
        const int row = cc >> 2;
        const int blk = cc & 3;
        __half h16[16];
#pragma unroll
        for (int q = 0; q < 16; q++)
            h16[q] = __float2half(t[row][blk * 16 + orig16(q)]);
        __half* dst = g_xh + ((size_t)b * S_ + j0 + row) * D_ + h * 64 + blk * 16;
        *(uint4*)dst       = *(uint4*)&h16[0];
        *(uint4*)(dst + 8) = *(uint4*)&h16[8];
    }
}

// ---------------------------------------------------------------------------
// Kernel 1: fused q/k projection, fp16 m16n8k16, 3-stage single-sync.
// ---------------------------------------------------------------------------
#define PJ_LDH   48
#define PJ_MAT_B (128 * 96)
#define PJ_STG_B (2 * PJ_MAT_B)              // 24576 B per stage
#define PJ_SMEM  73728                       // 3 stages (>= Cs 67584)
#define PJ_LDC   132

__global__ __launch_bounds__(256, 2) void proj_kernel(const float* __restrict__ bias)
{
    extern __shared__ char smc[];
    float* Cs = (float*)smc;
    __shared__ float sBias[128];

    const int tid = threadIdx.x;
    const int m0 = blockIdx.y * 128;
    const int n0 = blockIdx.x * 128;
    const int wid = tid >> 5;
    const int lane = tid & 31;
    const int gid = lane >> 2;
    const int tig = lane & 3;
    const int wm = wid & 1;
    const int wn = wid >> 1;

    if (tid < 128) sBias[tid] = bias[n0 + tid];

    float acc[4][4][4];
#pragma unroll
    for (int mi = 0; mi < 4; mi++)
#pragma unroll
        for (int ni = 0; ni < 4; ni++)
#pragma unroll
            for (int r = 0; r < 4; r++) acc[mi][ni][r] = 0.f;

    const uint32_t sbase = smem_u32(smc);

    auto load_stage = [&](int s, int k0) {
        const uint32_t aB = sbase + s * PJ_STG_B;
        const uint32_t bB = aB + PJ_MAT_B;
#pragma unroll
        for (int i = 0; i < 2; i++) {
            const int idx = tid + i * 256;
            const int row = idx >> 2, c = idx & 3;
            CP_ASYNC16(aB + row * 96 + c * 16,
                       g_xh + (size_t)(m0 + row) * D_ + k0 + c * 8);
        }
#pragma unroll
        for (int i = 0; i < 2; i++) {
            const int idx = tid + i * 256;
            const int row = idx >> 2, c = idx & 3;
            CP_ASYNC16(bB + row * 96 + c * 16,
                       g_wh + (size_t)(n0 + row) * D_ + k0 + c * 8);
        }
        CP_COMMIT();
    };

    load_stage(0, 0);
    load_stage(1, 32);

    const int NKC = D_ / 32;
    for (int kc = 0; kc < NKC; kc++) {
        if (kc < NKC - 1) CP_WAIT(1); else CP_WAIT(0);
        __syncthreads();
        if (kc + 2 < NKC) load_stage((kc + 2) % 3, (kc + 2) * 32);

        const __half* A  = (const __half*)(smc + (kc % 3) * PJ_STG_B);
        const __half* Bp = A + 128 * PJ_LDH;
#pragma unroll
        for (int kg = 0; kg < 2; kg++) {
            uint32_t a[4][4];
#pragma unroll
            for (int mi = 0; mi < 4; mi++) {
                const __half* ra = A + (wm * 64 + mi * 16 + gid) * PJ_LDH + kg * 16 + tig * 4;
                uint2 lo = *(const uint2*)ra;
                uint2 hi = *(const uint2*)(ra + 8 * PJ_LDH);
                a[mi][0] = lo.x; a[mi][1] = hi.x; a[mi][2] = lo.y; a[mi][3] = hi.y;
            }
            uint32_t bf[4][2];
#pragma unroll
            for (int ni = 0; ni < 4; ni++) {
                const __half* rb = Bp + (wn * 32 + ni * 8 + gid) * PJ_LDH + kg * 16 + tig * 4;
                uint2 f = *(const uint2*)rb;
                bf[ni][0] = f.x; bf[ni][1] = f.y;
            }
#pragma unroll
            for (int mi = 0; mi < 4; mi++)
#pragma unroll
                for (int ni = 0; ni < 4; ni++)
                    mma_f16(acc[mi][ni], a[mi], bf[ni]);
        }
    }
    __syncthreads();

    // ---- epilogue: acc -> Cs -> perm16 fp16 scatter to g_qh / g_kh ----
#pragma unroll
    for (int mi = 0; mi < 4; mi++)
#pragma unroll
        for (int ni = 0; ni < 4; ni++) {
            const int r = wm * 64 + mi * 16 + gid;
            const int c = wn * 32 + ni * 8 + 2 * tig;
            *(float2*)&Cs[r * PJ_LDC + c]       = make_float2(acc[mi][ni][0], acc[mi][ni][1]);
            *(float2*)&Cs[(r + 8) * PJ_LDC + c] = make_float2(acc[mi][ni][2], acc[mi][ni][3]);
        }
    __syncthreads();

    {
        const int r    = tid >> 1;
        const int hsel = tid & 1;
        const int m = m0 + r;
        const int bb = m >> 11;
        const int s_idx = m & 2047;
        const int hh = n0 >> 7;
        const size_t base = (((size_t)bb * H_ + hh) * S_ + s_idx) * DH;
        const float* cr = Cs + r * PJ_LDC;
#pragma unroll
        for (int bi = 0; bi < 2; bi++) {
            const int bk = hsel * 2 + bi;
            __half qh[16], kh[16];
#pragma unroll
            for (int q = 0; q < 16; q++) {
                const int dorig = bk * 16 + orig16(q);
                qh[q] = __float2half(cr[2 * dorig]     + sBias[2 * dorig]);
                kh[q] = __float2half(cr[2 * dorig + 1] + sBias[2 * dorig + 1]);
            }
            *(uint4*)(g_qh + base + bk * 16)     = *(uint4*)&qh[0];
            *(uint4*)(g_qh + base + bk * 16 + 8) = *(uint4*)&qh[8];
            *(uint4*)(g_kh + base + bk * 16)     = *(uint4*)&kh[0];
            *(uint4*)(g_kh + base + bk * 16 + 8) = *(uint4*)&kh[8];
        }
    }
}

// ---------------------------------------------------------------------------
// Kernel 2a: per-chunk ksum partials (512 blocks, 64 j-rows each);
// 2b: kadj folds mean + scale*log2e into K (reads the 8 partials directly)
// ---------------------------------------------------------------------------
__global__ __launch_bounds__(256) void ksum1_kernel()
{
    __shared__ float red[256];
    const int blk = blockIdx.x;              // bh*8 + c
    const int bh = blk >> 3, c = blk & 7;
    const int t = threadIdx.x;
    const int d = t & 63;
    const int sub = t >> 6;                  // 0..3
    const __half* base = g_kh + (size_t)bh * S_ * DH;
    const int j0 = c * 256 + sub * 64, j1 = j0 + 64;
    float s = 0.f;
    for (int j = j0; j < j1; j++) s += __half2float(base[(size_t)j * DH + d]);
    red[t] = s;
    __syncthreads();
    if (t < 64)
        g_kpart[blk * 64 + t] = red[t] + red[64 + t] + red[128 + t] + red[192 + t];
}

__global__ __launch_bounds__(256) void kadj_kernel()
{
    __shared__ float sk[64];
    const int bh  = blockIdx.y;
    const int seg = blockIdx.x;
    const int tid = threadIdx.x;
    if (tid < 64) {
        float s = 0.f;
#pragma unroll
        for (int c = 0; c < 8; c++) s += g_kpart[(bh * 8 + c) * 64 + tid];
        sk[tid] = s * (1.f / (float)S_);
    }
    __syncthreads();
    const float KF = 0.125f * 1.4426950408889634f;   // SCALE * log2(e)
    __half* base = g_kh + (size_t)bh * S_ * DH + (size_t)seg * 256 * DH;
    for (int i = tid; i < 2048; i += 256) {
        __half h[8];
        *(uint4*)h = *(const uint4*)(base + i * 8);
        const int p0 = (i * 8) & 63;
#pragma unroll
        for (int q = 0; q < 8; q++)
            h[q] = __float2half((__half2float(h[q]) - sk[p0 + q]) * KF);
        *(uint4*)(base + i * 8) = *(uint4*)h;
    }
}

// ---------------------------------------------------------------------------
// Kernel 3: fused attention -- R11 structure (proven 367 us) + Q fragments
// hoisted to registers (aq[4][4] = 16 regs; fits 128-reg 2-CTA cap).
// 256 threads, 2 CTAs/SM, 8 warps wm=wid (16 q-rows, full j=64 per iter),
// 2-stage K/V pipeline, strides 160 B, mean pre-folded into K, half2 selu.
// ---------------------------------------------------------------------------
#define AT_LDH  80
#define AT_QS_B (128 * AT_LDH * 2)           // 20480
#define AT_KS_B (64 * AT_LDH * 2)            // 10240
#define AT_PS_OFF (AT_QS_B + 4 * AT_KS_B)    // 61440
#define AT_SMEM (AT_PS_OFF + 128 * 68 * 4)   // 96256

__global__ __launch_bounds__(256, 2) void attn_kernel(float* __restrict__ out)
{
    extern __shared__ char smc[];
    __half* qs  = (__half*)smc;
    __half* ksb = (__half*)(smc + AT_QS_B);
    __half* vsb = (__half*)(smc + AT_QS_B + 2 * AT_KS_B);
    float*  ps  = (float*)(smc + AT_PS_OFF);

    const int b  = blockIdx.z;
    const int h  = blockIdx.y;
    const int s0 = blockIdx.x * 128;
    const int tid = threadIdx.x;
    const int wid = tid >> 5;
    const int lane = tid & 31;
    const int gid = lane >> 2;
    const int tig = lane & 3;
    const int wm = wid;

    const size_t bh = (size_t)b * H_ + h;
    const __half* qg = g_qh + bh * S_ * DH;
    const __half* kg = g_kh + bh * S_ * DH;
    const __half* vg = g_vh + bh * DH * S_;

    const uint32_t qsB = smem_u32(qs);
    const uint32_t ksB = smem_u32(ksb);
    const uint32_t vsB = smem_u32(vsb);

    auto load_kv = [&](int buf, int j0) {
        const uint32_t kB = ksB + buf * AT_KS_B;
        const uint32_t vB = vsB + buf * AT_KS_B;
#pragma unroll
        for (int i = 0; i < 2; i++) {
            const int idx = tid + i * 256;
            const int row = idx >> 3, c = idx & 7;
            CP_ASYNC16(kB + row * 160 + c * 16,
                       kg + (size_t)(j0 + row) * DH + c * 8);
        }
#pragma unroll
        for (int i = 0; i < 2; i++) {
            const int idx = tid + i * 256;
            const int row = idx >> 3, c = idx & 7;   // row = d
            CP_ASYNC16(vB + row * 160 + c * 16,
                       vg + (size_t)row * S_ + j0 + c * 8);
        }
    };

    // ---- prologue: Q + K/V tile 0, then hoist Q fragments ----
#pragma unroll
    for (int i = 0; i < 4; i++) {
        const int idx = tid + i * 256;
        const int row = idx >> 3, c = idx & 7;
        CP_ASYNC16(qsB + row * 160 + c * 16,
                   qg + (size_t)(s0 + row) * DH + c * 8);
    }
    load_kv(0, 0);
    CP_COMMIT();
    CP_WAIT(0);
    __syncthreads();

    uint32_t aq[4][4];
#pragma unroll
    for (int g = 0; g < 4; g++) {
        const __half* ra = qs + (wm * 16 + gid) * AT_LDH + g * 16 + tig * 4;
        uint2 lo = *(const uint2*)ra;
        uint2 hi = *(const uint2*)(ra + 8 * AT_LDH);
        aq[g][0] = lo.x; aq[g][1] = hi.x; aq[g][2] = lo.y; aq[g][3] = hi.y;
    }

    float oacc[8][4];
#pragma unroll
    for (int nt = 0; nt < 8; nt++)
#pragma unroll
        for (int r = 0; r < 4; r++) oacc[nt][r] = 0.f;

    const int NJT = S_ / 64;                 // 32
    for (int jt = 0; jt < NJT; jt++) {
        const int buf = jt & 1;
        if (jt > 0) {
            CP_WAIT(0);
            __syncthreads();                 // K/V[buf] ready; reads of buf^1 done
        }
        if (jt + 1 < NJT) {
            load_kv(buf ^ 1, (jt + 1) * 64);
            CP_COMMIT();
        }

        const __half* kss = ksb + buf * (64 * AT_LDH);
        const __half* vss = vsb + buf * (64 * AT_LDH);

        // ---- d = Q K'^T : 16m x 64j  (d = log2e * (scale*qk - mean)) ----
        float d[8][4];
#pragma unroll
        for (int tn = 0; tn < 8; tn++)
#pragma unroll
            for (int r = 0; r < 4; r++) d[tn][r] = 0.f;

#pragma unroll
        for (int g = 0; g < 4; g++) {
#pragma unroll
            for (int tn = 0; tn < 8; tn++) {
                const __half* rb = kss + (tn * 8 + gid) * AT_LDH + g * 16 + tig * 4;
                uint2 f = *(const uint2*)rb;
                uint32_t bb2[2] = { f.x, f.y };
                mma_f16(d[tn], aq[g], bb2);
            }
        }

        // ---- half2 selu; packs feed AV A-fragments directly ----
        uint32_t av[4][4];
#pragma unroll
        for (int u = 0; u < 4; u++) {
            av[u][0] = seluh2(d[2*u][0],   d[2*u][1]);
            av[u][1] = seluh2(d[2*u][2],   d[2*u][3]);
            av[u][2] = seluh2(d[2*u+1][0], d[2*u+1][1]);
            av[u][3] = seluh2(d[2*u+1][2], d[2*u+1][3]);
        }

        // ---- oacc += A @ V  (V^T j-perm16 fragments) ----
#pragma unroll
        for (int nt = 0; nt < 8; nt++) {
#pragma unroll
            for (int u = 0; u < 4; u++) {
                const __half* rv = vss + (nt * 8 + gid) * AT_LDH + u * 16 + tig * 4;
                uint2 f = *(const uint2*)rv;
                uint32_t bb2[2] = { f.x, f.y };
                mma_f16(oacc[nt], av[u], bb2);
            }
        }
    }

    // ---- epilogue: oacc -> ps -> coalesced gmem ----
    __syncthreads();
#pragma unroll
    for (int nt = 0; nt < 8; nt++) {
        *(float2*)(ps + (wm * 16 + gid) * 68 + nt * 8 + 2 * tig) =
            make_float2(oacc[nt][0], oacc[nt][1]);
        *(float2*)(ps + (wm * 16 + gid + 8) * 68 + nt * 8 + 2 * tig) =
            make_float2(oacc[nt][2], oacc[nt][3]);
    }
    __syncthreads();
    {
        const float OS = 0.022097086912079608f;   // 2048^-0.5
        const int r = tid >> 1;
        const int seg = (tid & 1) * 32;
        const float* pr = ps + r * 68 + seg;
        float* dst = out + ((size_t)b * S_ + s0 + r) * D_ + h * DH + seg;
#pragma unroll
        for (int v = 0; v < 8; v++) {
            float4 o4 = make_float4(pr[v*4+0] * OS, pr[v*4+1] * OS,
                                    pr[v*4+2] * OS, pr[v*4+3] * OS);
            *(float4*)(dst + v * 4) = o4;
        }
    }
}

// ---------------------------------------------------------------------------
extern "C" void kernel_launch(void* const* d_in, const int* in_sizes, int n_in,
                              void* d_out, int out_size)
{
    const float* x    = (const float*)d_in[0];
    const float* W    = (const float*)d_in[1];
    const float* bias = (const float*)d_in[2];
    float* out = (float*)d_out;

    cudaFuncSetAttribute(proj_kernel,
                         cudaFuncAttributeMaxDynamicSharedMemorySize, PJ_SMEM);
    cudaFuncSetAttribute(attn_kernel,
                         cudaFuncAttributeMaxDynamicSharedMemorySize, AT_SMEM);

    const int cvt_blocks = (int)((WB16 + 255) / 256);
    cvt_kernel<<<cvt_blocks, 256>>>(W);

    dim3 vg(S_ / 128, H_, B_);                       // (16, 16, 4)
    vtr_kernel<<<vg, 256>>>(x);

    dim3 pg(D_ * 2 / 128, (B_ * S_) / 128);          // (16, 64)
    proj_kernel<<<pg, 256, PJ_SMEM>>>(bias);

    ksum1_kernel<<<512, 256>>>();

    dim3 kg(8, B_ * H_);                             // (8, 64)
    kadj_kernel<<<kg, 256>>>();

    dim3 ag(S_ / 128, H_, B_);                       // (16, 16, 4)
    attn_kernel<<<ag, 256, AT_SMEM>>>(out);
}